// round 1
// baseline (speedup 1.0000x reference)
#include <cuda_runtime.h>

// ---------------- problem constants ----------------
#define NROWS     2048
#define RROWS     4          // batch rows per CTA
#define NTHREADS  512
#define SPONGE_N  1024
#define HALFW     512
#define QUARTW    256
#define ACT_N     256
#define DEPTH_N   8
#define BDEPTH_N  10
#define BF_SIZE   3072
#define BF_HALF   1536
#define BF_QUART  768
#define BF_DEPTH  12
#define PADF      16         // 64B pad at half boundary -> conflict-free LDS.128

#define SP_STRIDE   (SPONGE_N*RROWS + PADF)     // 4112 floats
#define MEM_OFF     (2*SP_STRIDE)               // 8224 floats
#define BF_STRIDE   (BF_SIZE*RROWS + PADF)      // 12304 floats
#define SMEM_FLOATS (2*BF_STRIDE)               // 24608 floats = 98432 B

// ---------------- precomputed tables ----------------
__device__ float2 g_rot  [DEPTH_N*BDEPTH_N*HALFW];  // (cos,sin) sponge butterflies
__device__ float2 g_bfrot[BF_DEPTH*BF_HALF];        // (cos,sin) final butterfly
__device__ float4 g_act  [DEPTH_N*ACT_N];           // (bias, c, t, 1/c)
__device__ int    g_recall[DEPTH_N*ACT_N];
__device__ int    g_outidx[2048];

// Prep: sincos tables + activation constants + index-dtype decode.
__global__ void prep_kernel(const float* __restrict__ angles,
                            const float* __restrict__ bf_angles,
                            const float* __restrict__ act_bias,
                            const float* __restrict__ act_curv,
                            const void*  __restrict__ recall_raw,
                            const void*  __restrict__ out_raw)
{
    int i = blockIdx.x * blockDim.x + threadIdx.x;
    const int NROT = DEPTH_N*BDEPTH_N*HALFW;       // 40960
    const int NBF  = BF_DEPTH*BF_HALF;             // 18432
    if (i < NROT) {
        float s, c; sincosf(angles[i], &s, &c);
        g_rot[i] = make_float2(c, s);
    } else if (i < NROT + NBF) {
        int j = i - NROT;
        float s, c; sincosf(bf_angles[j], &s, &c);
        g_bfrot[j] = make_float2(c, s);
    } else if (i < NROT + NBF + DEPTH_N*ACT_N) {
        int k = i - NROT - NBF;
        float cu = act_curv[k];
        float c  = 0.5f*(cu + sqrtf(cu*cu + 1.0f));
        g_act[k] = make_float4(act_bias[k], c, 0.25f*3.14159265358979323846f/c, 1.0f/c);
    }
    // dtype-robust index decode (int32 vs int64). output_mem_idx is strictly
    // increasing, so if the odd int32 words of the first elements are all zero
    // it must be int64 little-endian.
    if (i < 2048) {
        const int* o32 = (const int*)out_raw;
        bool is64 = (o32[1]==0 && o32[3]==0 && o32[5]==0 && o32[7]==0);
        if (is64) {
            g_outidx[i] = (int)((const long long*)out_raw)[i];
            g_recall[i] = (int)((const long long*)recall_raw)[i];
        } else {
            g_outidx[i] = o32[i];
            g_recall[i] = ((const int*)recall_raw)[i];
        }
    }
}

// ---------------- shared-memory indexing ----------------
__device__ __forceinline__ int idx_s(int p) { return p*RROWS + ((p>>9)<<4); }          // pad at 512
__device__ __forceinline__ int idx_b(int p) { return p*RROWS + ((p>=BF_HALF)?PADF:0); } // pad at 1536

// piecewise activation
__device__ __forceinline__ float actf(float x, float c, float tt, float invc) {
    const float OOS2 = 0.70710678118654752f;   // 1/sqrt(2)
    float r = invc*(OOS2 - __cosf(0.78539816339744831f + c*x));  // mid
    if (x >  tt) r = invc*OOS2 + (x - tt);   // y0 + m0*(x-t), m0=1
    if (x < -tt) r = invc*(OOS2 - 1.0f);     // y1, m1=0
    return r;
}

#define ROT4(o1,o2,cs,a,b)                              \
    o1.x = cs.x*a.x + cs.y*b.x;  o2.x = cs.x*b.x - cs.y*a.x; \
    o1.y = cs.x*a.y + cs.y*b.y;  o2.y = cs.x*b.y - cs.y*a.y; \
    o1.z = cs.x*a.z + cs.y*b.z;  o2.z = cs.x*b.z - cs.y*a.z; \
    o1.w = cs.x*a.w + cs.y*b.w;  o2.w = cs.x*b.w - cs.y*a.w;

__global__ void __launch_bounds__(NTHREADS)
sponge_kernel(const float* __restrict__ X,
              const float* __restrict__ scales,
              float* __restrict__ out)
{
    extern __shared__ float sb[];
    const int t    = threadIdx.x;
    const int row0 = blockIdx.x * RROWS;
    float* const MEMB = sb + MEM_OFF;

    // ---- load X * scales into sponge buffer 0, row-minor ----
    {
        float sc0 = scales[t], sc1 = scales[t + HALFW];
        int i0 = idx_s(t), i1 = idx_s(t + HALFW);
        #pragma unroll
        for (int r = 0; r < RROWS; r++) {
            const float* xr = X + (size_t)(row0 + r) * SPONGE_N;
            sb[i0 + r] = xr[t]          * sc0;
            sb[i1 + r] = xr[t + HALFW]  * sc1;
        }
    }
    __syncthreads();

    // per-thread constant butterfly addresses (sponge phase)
    const int p0s = (t >> 1) + ((t & 1) << 9);
    const int a0  = idx_s(p0s);
    const int a1  = idx_s(p0s + QUARTW);
    const int w0  = idx_s(t);
    const int w1  = idx_s(t + HALFW);

    int cur = 0;
    for (int d = 0; d < DEPTH_N; d++) {
        // ---- 10 butterfly layers ----
        const float2* rot = g_rot + d*(BDEPTH_N*HALFW) + t;
        #pragma unroll
        for (int j = 0; j < BDEPTH_N; j++) {
            float2 cs = __ldg(&rot[j*HALFW]);
            const float* IN  = sb + cur*SP_STRIDE;
            float*       OUT = sb + (cur^1)*SP_STRIDE;
            float4 a = *(const float4*)(IN + a0);
            float4 b = *(const float4*)(IN + a1);
            float4 o1, o2;
            ROT4(o1, o2, cs, a, b);
            *(float4*)(OUT + w0) = o1;
            *(float4*)(OUT + w1) = o2;
            cur ^= 1;
            __syncthreads();
        }
        float* S = sb + cur*SP_STRIDE;   // cur==0 again (10 layers)

        // ---- activation / mem store / recall ----
        int ja = t >> 1;
        float4 ap = g_act[d*ACT_N + ja];          // bias, c, t, 1/c
        float4 x  = *(const float4*)(S + idx_s(HALFW + ja));
        float sgn = (t & 1) ? -1.0f : 1.0f;
        float4 o;
        o.x = actf(sgn*(x.x + ap.x), ap.y, ap.z, ap.w);
        o.y = actf(sgn*(x.y + ap.x), ap.y, ap.z, ap.w);
        o.z = actf(sgn*(x.z + ap.x), ap.y, ap.z, ap.w);
        o.w = actf(sgn*(x.w + ap.x), ap.y, ap.z, ap.w);

        float4 mv = *(const float4*)(S + w0);
        *(float4*)(MEMB + (d*HALFW + t)*RROWS) = mv;   // mem[i*512+t] = sponge[t]

        float4 kv = make_float4(0.f,0.f,0.f,0.f);
        if (t < QUARTW) kv = *(const float4*)(S + idx_s(3*QUARTW + t));
        __syncthreads();

        *(float4*)(S + w0) = o;                        // act_out -> [0,512)
        if (t < QUARTW) {
            *(float4*)(S + idx_s(HALFW + t)) = kv;     // old [768,1024) -> [512,768)
        } else {
            int q  = t - QUARTW;
            int mi = g_recall[d*ACT_N + q];
            *(float4*)(S + idx_s(3*QUARTW + q)) = *(const float4*)(MEMB + mi*RROWS);
        }
        __syncthreads();
    }

    // ---- build pre = [mem[out_idx] (2048), sponge (1024)] in BF buffer 0 ----
    {
        float4 s0 = *(const float4*)(sb + w0);         // sponge lives in buffer 0
        float4 s1 = *(const float4*)(sb + w1);
        __syncthreads();                               // reads done before clobber
        #pragma unroll
        for (int p = 0; p < 2048; p += NTHREADS) {
            int pp = p + t;
            int oi = g_outidx[pp];
            *(float4*)(sb + idx_b(pp)) = *(const float4*)(MEMB + oi*RROWS);
        }
        __syncthreads();                               // mem reads done before clobbering mem head
        *(float4*)(sb + idx_b(2048 + t))         = s0;
        *(float4*)(sb + idx_b(2048 + HALFW + t)) = s1;
        __syncthreads();
    }

    // ---- final 12-layer butterfly on 3072 ----
    int c2 = 0;
    for (int j = 0; j < BF_DEPTH; j++) {
        const float* IN  = sb + c2*BF_STRIDE;
        float*       OUT = sb + (c2^1)*BF_STRIDE;
        #pragma unroll
        for (int kk0 = 0; kk0 < BF_HALF; kk0 += NTHREADS) {
            int kk = kk0 + t;
            float2 cs = __ldg(&g_bfrot[j*BF_HALF + kk]);
            int p0 = (kk >> 1) + (kk & 1)*BF_HALF;
            float4 a = *(const float4*)(IN + idx_b(p0));
            float4 b = *(const float4*)(IN + idx_b(p0 + BF_QUART));
            float4 o1, o2;
            ROT4(o1, o2, cs, a, b);
            *(float4*)(OUT + idx_b(kk))           = o1;
            *(float4*)(OUT + idx_b(kk + BF_HALF)) = o2;
        }
        c2 ^= 1;
        __syncthreads();
    }

    // result in buffer 0 (12 layers, even). Emit first 512 columns.
    {
        float4 v = *(const float4*)(sb + idx_b(t));    // t < 512 -> t*4
        out[(size_t)(row0 + 0)*HALFW + t] = v.x;
        out[(size_t)(row0 + 1)*HALFW + t] = v.y;
        out[(size_t)(row0 + 2)*HALFW + t] = v.z;
        out[(size_t)(row0 + 3)*HALFW + t] = v.w;
    }
}

extern "C" void kernel_launch(void* const* d_in, const int* in_sizes, int n_in,
                              void* d_out, int out_size)
{
    (void)in_sizes; (void)n_in; (void)out_size;
    const float* X          = (const float*)d_in[0];
    const float* scales     = (const float*)d_in[1];
    const float* angles     = (const float*)d_in[2];
    const float* act_bias   = (const float*)d_in[3];
    // d_in[4] = act_activation (unused by reference)
    const float* act_curv   = (const float*)d_in[5];
    const float* bf_angles  = (const float*)d_in[6];
    // d_in[7] = shuffle_perm (deterministic riffle, computed inline)
    const void*  recall_raw = d_in[8];
    const void*  out_raw    = d_in[9];
    // d_in[10] = bf_perm (deterministic riffle, computed inline)
    float* out = (float*)d_out;

    const int totalPrep = DEPTH_N*BDEPTH_N*HALFW + BF_DEPTH*BF_HALF + DEPTH_N*ACT_N; // 61440
    prep_kernel<<<(totalPrep + 255)/256, 256>>>(angles, bf_angles, act_bias, act_curv,
                                                recall_raw, out_raw);

    size_t smem = SMEM_FLOATS * sizeof(float);   // 98432 B
    cudaFuncSetAttribute(sponge_kernel, cudaFuncAttributeMaxDynamicSharedMemorySize, (int)smem);
    sponge_kernel<<<NROWS/RROWS, NTHREADS, smem>>>(X, scales, out);
}